// round 1
// baseline (speedup 1.0000x reference)
#include <cuda_runtime.h>
#include <cuda_bf16.h>
#include <math.h>

// ---------------------------------------------------------------------------
// Problem constants
// ---------------------------------------------------------------------------
#define BATCH     1024
#define X_COLS    8751          // N_IMG + 3
#define N_IMG     8748          // 3*54*54
#define IMG_C     3
#define IMG_H     54
#define IMG_W     54

#define OC1       32
#define O1        52            // 54 - 2
#define P1        26            // pooled
#define H1_PER    (OC1 * P1 * P1)      // 21632

#define OC2       64
#define O2        24            // 26 - 2
#define P2        12
#define H2_PER    (OC2 * P2 * P2)      // 9216

#define FCN_IN    9219
#define FCN_OUT   6

// ---------------------------------------------------------------------------
// Device scratch (no allocations allowed)
// ---------------------------------------------------------------------------
__device__ float g_h1[(size_t)BATCH * H1_PER];   // ~88.6 MB
__device__ float g_h2[(size_t)BATCH * H2_PER];   // ~37.7 MB

// ---------------------------------------------------------------------------
// Kernel 1: conv1 (3->32, 3x3 valid) + bias + relu + maxpool2
// One block per image. Image + weights staged in static smem.
// ---------------------------------------------------------------------------
__global__ __launch_bounds__(256) void conv1_pool_kernel(
    const float* __restrict__ x,
    const float* __restrict__ w1,
    const float* __restrict__ b1)
{
    __shared__ float simg[N_IMG];        // 34992 B
    __shared__ float sw[OC1 * 27];       // 3456 B
    __shared__ float sb[OC1];

    const int bimg = blockIdx.x;
    const float* xp = x + (size_t)bimg * X_COLS;

    for (int i = threadIdx.x; i < N_IMG; i += 256) simg[i] = xp[i];
    for (int i = threadIdx.x; i < OC1 * 27; i += 256) sw[i] = w1[i];
    if (threadIdx.x < OC1) sb[threadIdx.x] = b1[threadIdx.x];
    __syncthreads();

    float* hout = g_h1 + (size_t)bimg * H1_PER;

    for (int idx = threadIdx.x; idx < H1_PER; idx += 256) {
        const int oc  = idx / (P1 * P1);
        const int pos = idx % (P1 * P1);
        const int py = pos / P1, px = pos % P1;
        const int y0 = py * 2, x0 = px * 2;

        const float bias = sb[oc];
        float v00 = bias, v01 = bias, v10 = bias, v11 = bias;
        const float* wp = sw + oc * 27;

        #pragma unroll
        for (int ic = 0; ic < IMG_C; ic++) {
            // 4x4 input patch (even float offset -> float2 aligned)
            float p[4][4];
            const float* ip = simg + ic * (IMG_H * IMG_W) + y0 * IMG_W + x0;
            #pragma unroll
            for (int i = 0; i < 4; i++) {
                const float2* rp = reinterpret_cast<const float2*>(ip + i * IMG_W);
                float2 q0 = rp[0];
                float2 q1 = rp[1];
                p[i][0] = q0.x; p[i][1] = q0.y; p[i][2] = q1.x; p[i][3] = q1.y;
            }
            #pragma unroll
            for (int ky = 0; ky < 3; ky++) {
                #pragma unroll
                for (int kx = 0; kx < 3; kx++) {
                    const float w = wp[ic * 9 + ky * 3 + kx];
                    v00 = fmaf(p[ky][kx],     w, v00);
                    v01 = fmaf(p[ky][kx + 1], w, v01);
                    v10 = fmaf(p[ky + 1][kx], w, v10);
                    v11 = fmaf(p[ky + 1][kx + 1], w, v11);
                }
            }
        }
        float m = fmaxf(fmaxf(v00, v01), fmaxf(v10, v11));
        hout[idx] = fmaxf(m, 0.0f);   // relu(max) == max(relu) for maxpool
    }
}

// ---------------------------------------------------------------------------
// Kernel 2: conv2 (32->64, 3x3 valid) + bias + relu + maxpool2
// One block per image. Input tile (86.5 KB) + weights (73.7 KB) in dyn smem.
// 4-way output-channel blocking: one 4x4 patch feeds 4*36 = 144 FMAs.
// ---------------------------------------------------------------------------
#define SMEM2_FLOATS (H1_PER + OC2 * 32 * 9 + OC2)       // 21632+18432+64 = 40128
#define SMEM2_BYTES  (SMEM2_FLOATS * 4)                  // 160512

__global__ __launch_bounds__(256) void conv2_pool_kernel(
    const float* __restrict__ w2,
    const float* __restrict__ b2)
{
    extern __shared__ float s2[];
    float* sin = s2;                  // [32][26][26]
    float* sw  = s2 + H1_PER;         // [64][32][9]
    float* sb  = sw + OC2 * 32 * 9;   // [64]

    const int bimg = blockIdx.x;
    const float* hp = g_h1 + (size_t)bimg * H1_PER;

    // vectorized stage-in (both counts divisible by 4; global bases 16B-aligned)
    {
        const float4* src = reinterpret_cast<const float4*>(hp);
        float4* dst = reinterpret_cast<float4*>(sin);
        for (int i = threadIdx.x; i < H1_PER / 4; i += 256) dst[i] = src[i];
        const float4* wsrc = reinterpret_cast<const float4*>(w2);
        float4* wdst = reinterpret_cast<float4*>(sw);
        for (int i = threadIdx.x; i < (OC2 * 32 * 9) / 4; i += 256) wdst[i] = wsrc[i];
        if (threadIdx.x < OC2) sb[threadIdx.x] = b2[threadIdx.x];
    }
    __syncthreads();

    float* hout = g_h2 + (size_t)bimg * H2_PER;

    // 16 oc-groups * 144 pooled positions = 2304 work items
    for (int idx = threadIdx.x; idx < (OC2 / 4) * (P2 * P2); idx += 256) {
        const int g   = idx / (P2 * P2);
        const int pos = idx % (P2 * P2);
        const int oc0 = g * 4;
        const int py = pos / P2, px = pos % P2;
        const int y0 = py * 2, x0 = px * 2;

        float acc[4][4];
        #pragma unroll
        for (int o = 0; o < 4; o++) {
            const float bias = sb[oc0 + o];
            acc[o][0] = bias; acc[o][1] = bias; acc[o][2] = bias; acc[o][3] = bias;
        }

        #pragma unroll 1
        for (int ic = 0; ic < 32; ic++) {
            float p[4][4];
            const float* ip = sin + ic * (P1 * P1) + y0 * P1 + x0;
            #pragma unroll
            for (int i = 0; i < 4; i++) {
                const float2* rp = reinterpret_cast<const float2*>(ip + i * P1);
                float2 q0 = rp[0];
                float2 q1 = rp[1];
                p[i][0] = q0.x; p[i][1] = q0.y; p[i][2] = q1.x; p[i][3] = q1.y;
            }
            #pragma unroll
            for (int o = 0; o < 4; o++) {
                const float* wp = sw + (oc0 + o) * 288 + ic * 9;
                #pragma unroll
                for (int ky = 0; ky < 3; ky++) {
                    #pragma unroll
                    for (int kx = 0; kx < 3; kx++) {
                        const float w = wp[ky * 3 + kx];
                        acc[o][0] = fmaf(p[ky][kx],         w, acc[o][0]);
                        acc[o][1] = fmaf(p[ky][kx + 1],     w, acc[o][1]);
                        acc[o][2] = fmaf(p[ky + 1][kx],     w, acc[o][2]);
                        acc[o][3] = fmaf(p[ky + 1][kx + 1], w, acc[o][3]);
                    }
                }
            }
        }
        #pragma unroll
        for (int o = 0; o < 4; o++) {
            float m = fmaxf(fmaxf(acc[o][0], acc[o][1]), fmaxf(acc[o][2], acc[o][3]));
            hout[(oc0 + o) * (P2 * P2) + pos] = fmaxf(m, 0.0f);
        }
    }
}

// ---------------------------------------------------------------------------
// Kernel 3: fcn (6x9219) + relu, then per-image 2x2 SVD clip + KKT solve.
// One warp per image.
// ---------------------------------------------------------------------------
__global__ __launch_bounds__(256) void fcn_solve_kernel(
    const float* __restrict__ x,
    const float* __restrict__ fw,
    const float* __restrict__ fb,
    float* __restrict__ out)
{
    const int warp = (blockIdx.x * blockDim.x + threadIdx.x) >> 5;
    const int lane = threadIdx.x & 31;
    if (warp >= BATCH) return;

    const float* h = g_h2 + (size_t)warp * H2_PER;

    float a0 = 0.f, a1 = 0.f, a2 = 0.f, a3 = 0.f, a4 = 0.f, a5 = 0.f;
    const float* w0 = fw;
    const float* w1 = fw + FCN_IN;
    const float* w2 = fw + 2 * FCN_IN;
    const float* w3 = fw + 3 * FCN_IN;
    const float* w4 = fw + 4 * FCN_IN;
    const float* w5 = fw + 5 * FCN_IN;

    for (int j = lane; j < H2_PER; j += 32) {
        const float hv = h[j];
        a0 = fmaf(hv, w0[j], a0);
        a1 = fmaf(hv, w1[j], a1);
        a2 = fmaf(hv, w2[j], a2);
        a3 = fmaf(hv, w3[j], a3);
        a4 = fmaf(hv, w4[j], a4);
        a5 = fmaf(hv, w5[j], a5);
    }
    if (lane < 3) {   // appended scalars: speed, dest_distance, car_distance
        const float hv = x[(size_t)warp * X_COLS + N_IMG + lane];
        const int j = H2_PER + lane;
        a0 = fmaf(hv, w0[j], a0);
        a1 = fmaf(hv, w1[j], a1);
        a2 = fmaf(hv, w2[j], a2);
        a3 = fmaf(hv, w3[j], a3);
        a4 = fmaf(hv, w4[j], a4);
        a5 = fmaf(hv, w5[j], a5);
    }
    #pragma unroll
    for (int off = 16; off > 0; off >>= 1) {
        a0 += __shfl_xor_sync(0xFFFFFFFFu, a0, off);
        a1 += __shfl_xor_sync(0xFFFFFFFFu, a1, off);
        a2 += __shfl_xor_sync(0xFFFFFFFFu, a2, off);
        a3 += __shfl_xor_sync(0xFFFFFFFFu, a3, off);
        a4 += __shfl_xor_sync(0xFFFFFFFFu, a4, off);
        a5 += __shfl_xor_sync(0xFFFFFFFFu, a5, off);
    }

    if (lane != 0) return;

    // y = relu(h @ W^T + b)
    const float y0 = fmaxf(a0 + fb[0], 0.f);
    const float y1 = fmaxf(a1 + fb[1], 0.f);
    const float y2 = fmaxf(a2 + fb[2], 0.f);
    const float y3 = fmaxf(a3 + fb[3], 0.f);
    const float y4 = fmaxf(a4 + fb[4], 0.f);   // b[0]
    const float y5 = fmaxf(a5 + fb[5], 0.f);   // b[1]

    // A = [[y0, y1], [y2, y3]]
    float A00 = y0, A01 = y1, A10 = y2, A11 = y3;

    // Singular values (stable closed form)
    const float E = 0.5f * (A00 + A11);
    const float F = 0.5f * (A00 - A11);
    const float G = 0.5f * (A10 + A01);
    const float H = 0.5f * (A10 - A01);
    const float Qh = sqrtf(E * E + H * H);
    const float Rh = sqrtf(F * F + G * G);
    const float s1 = Qh + Rh;
    const float s2 = fabsf(Qh - Rh);

    if (s1 < 1e-30f) {
        // A == 0: S_p = [0.01, 0.01], LAPACK-style U = Vh = I  =>  A_p = 0.01 I
        A00 = 0.01f; A01 = 0.f; A10 = 0.f; A11 = 0.01f;
    } else {
        const float s2c = fmaxf(s2, 0.1f * s1);
        if (s2c > s2) {
            // need rank-1 correction: A_p = A + (s2c - s2) * u2 v2^T
            // v from A^T A, u from A A^T (top eigenvectors; gap >= 99% of lambda1 here)
            const float p  = A00 * A00 + A10 * A10;
            const float r  = A01 * A01 + A11 * A11;
            const float q  = A00 * A01 + A10 * A11;
            const float f  = 0.5f * (p - r);
            const float disc = sqrtf(f * f + q * q);
            float v1x, v1y;
            if (f >= 0.f) { v1x = disc + f; v1y = q; }
            else          { v1x = q;        v1y = disc - f; }
            float inv = rsqrtf(fmaxf(v1x * v1x + v1y * v1y, 1e-38f));
            v1x *= inv; v1y *= inv;
            float v2x = -v1y, v2y = v1x;

            const float pB = A00 * A00 + A01 * A01;
            const float rB = A10 * A10 + A11 * A11;
            const float qB = A00 * A10 + A01 * A11;
            const float fB = 0.5f * (pB - rB);
            const float discB = sqrtf(fB * fB + qB * qB);
            float u1x, u1y;
            if (fB >= 0.f) { u1x = discB + fB; u1y = qB; }
            else           { u1x = qB;         u1y = discB - fB; }
            inv = rsqrtf(fmaxf(u1x * u1x + u1y * u1y, 1e-38f));
            u1x *= inv; u1y *= inv;
            float u2x = -u1y, u2y = u1x;

            // fix relative sign so that u2^T A v2 = +s2
            const float t = u2x * (A00 * v2x + A01 * v2y) + u2y * (A10 * v2x + A11 * v2y);
            if (t < 0.f) { v2x = -v2x; v2y = -v2y; }

            const float d = s2c - s2;
            A00 = fmaf(d, u2x * v2x, A00);
            A01 = fmaf(d, u2x * v2y, A01);
            A10 = fmaf(d, u2y * v2x, A10);
            A11 = fmaf(d, u2y * v2y, A11);
        }
    }

    // KKT solve via Schur complement.
    // Q = diag(1, 0.5), p = (0, -1000)  =>  z0 = Qinv*(-p) = (0, 2000)
    // S = A Qinv A^T ; S lam = A z0 - b ; z = z0 - Qinv A^T lam
    const float qi0 = 1.0f, qi1 = 2.0f;
    const float S00 = A00 * A00 * qi0 + A01 * A01 * qi1;
    const float S01 = A00 * A10 * qi0 + A01 * A11 * qi1;
    const float S11 = A10 * A10 * qi0 + A11 * A11 * qi1;
    const float rhs0 = A01 * 2000.f - y4;
    const float rhs1 = A11 * 2000.f - y5;
    const float det = S00 * S11 - S01 * S01;
    const float idet = 1.0f / det;
    const float l0 = (S11 * rhs0 - S01 * rhs1) * idet;
    const float l1 = (S00 * rhs1 - S01 * rhs0) * idet;
    const float z0 = 0.f    - qi0 * (A00 * l0 + A10 * l1);
    const float z1 = 2000.f - qi1 * (A01 * l0 + A11 * l1);

    out[warp * 2 + 0] = z0;
    out[warp * 2 + 1] = z1;
}

// ---------------------------------------------------------------------------
// Launcher (graph-capturable: kernel launches only)
// ---------------------------------------------------------------------------
extern "C" void kernel_launch(void* const* d_in, const int* in_sizes, int n_in,
                              void* d_out, int out_size)
{
    const float* x   = (const float*)d_in[0];
    const float* w1  = (const float*)d_in[1];
    const float* b1  = (const float*)d_in[2];
    const float* w2  = (const float*)d_in[3];
    const float* b2  = (const float*)d_in[4];
    const float* fw  = (const float*)d_in[5];
    const float* fb  = (const float*)d_in[6];
    float* out = (float*)d_out;

    conv1_pool_kernel<<<BATCH, 256>>>(x, w1, b1);

    cudaFuncSetAttribute(conv2_pool_kernel,
                         cudaFuncAttributeMaxDynamicSharedMemorySize, SMEM2_BYTES);
    conv2_pool_kernel<<<BATCH, 256, SMEM2_BYTES>>>(w2, b2);

    fcn_solve_kernel<<<BATCH / 8, 256>>>(x, fw, fb, out);
}

// round 2
// speedup vs baseline: 1.5518x; 1.5518x over previous
#include <cuda_runtime.h>
#include <cuda_bf16.h>
#include <math.h>

typedef unsigned long long ull;

// ---------------------------------------------------------------------------
// Problem constants
// ---------------------------------------------------------------------------
#define BATCH     1024
#define X_COLS    8751
#define N_IMG     8748          // 3*54*54
#define IMG_HW    54

#define OC1       32
#define P1        26            // conv1 pooled
#define H1_PER    (OC1 * P1 * P1)      // 21632

#define OC2       64
#define P2        12            // conv2 pooled
#define H2_PER    (OC2 * P2 * P2)      // 9216

#define FCN_IN    9219
#define NTHREADS  288

// dynamic smem layout (floats):
//   [0, 21632)                 sH1  (conv1 output, 32x26x26)
//   [21632, 21632+18432)       sW2  (interleaved conv2 weights as float2[32pair][32ic][9])
//                              -- phase 1: this region holds the staged image (8748 floats)
//   [40064, 49280)             sH2  (conv2 output, 64x12x12)
#define SMEM_FLOATS (H1_PER + 18432 + H2_PER)   // 49280
#define SMEM_BYTES  (SMEM_FLOATS * 4)           // 197120

// ---------------------------------------------------------------------------
// f32x2 packed helpers (FFMA2 path — only reachable via PTX)
// ---------------------------------------------------------------------------
__device__ __forceinline__ ull fma2(ull a, ull b, ull c) {
    ull d;
    asm("fma.rn.f32x2 %0, %1, %2, %3;" : "=l"(d) : "l"(a), "l"(b), "l"(c));
    return d;
}
__device__ __forceinline__ ull dup2(float v) {
    ull r;
    asm("mov.b64 %0, {%1, %1};" : "=l"(r) : "f"(v));
    return r;
}
__device__ __forceinline__ void unpack2(ull v, float& lo, float& hi) {
    asm("mov.b64 {%0, %1}, %2;" : "=f"(lo), "=f"(hi) : "l"(v));
}

// ---------------------------------------------------------------------------
// One input-channel update of a 4x4 conv-output tile for 2 oc-pairs (4 ocs).
// base: top-left of 6x6 patch (float2-aligned). w0/w1: 9 packed weight pairs.
// ---------------------------------------------------------------------------
__device__ __forceinline__ void tile_ic(const float* __restrict__ base, int rstride,
                                        const ull* __restrict__ w0,
                                        const ull* __restrict__ w1,
                                        ull* __restrict__ a0, ull* __restrict__ a1)
{
    ull d[6][6];
    #pragma unroll
    for (int r = 0; r < 6; r++) {
        const float2* rp = reinterpret_cast<const float2*>(base + r * rstride);
        float2 q0 = rp[0], q1 = rp[1], q2 = rp[2];
        d[r][0] = dup2(q0.x); d[r][1] = dup2(q0.y);
        d[r][2] = dup2(q1.x); d[r][3] = dup2(q1.y);
        d[r][4] = dup2(q2.x); d[r][5] = dup2(q2.y);
    }
    #pragma unroll
    for (int ky = 0; ky < 3; ky++) {
        #pragma unroll
        for (int kx = 0; kx < 3; kx++) {
            const ull wa = w0[ky * 3 + kx];
            const ull wb = w1[ky * 3 + kx];
            #pragma unroll
            for (int r = 0; r < 4; r++) {
                #pragma unroll
                for (int c = 0; c < 4; c++) {
                    a0[r * 4 + c] = fma2(d[r + ky][c + kx], wa, a0[r * 4 + c]);
                    a1[r * 4 + c] = fma2(d[r + ky][c + kx], wb, a1[r * 4 + c]);
                }
            }
        }
    }
}

// pool (2x2 max) + relu + store for 2 oc-pairs of a 4x4 conv tile
template <int P>
__device__ __forceinline__ void pool_store(float* __restrict__ dst,
                                           const ull* __restrict__ a0,
                                           const ull* __restrict__ a1,
                                           int oc0, int py0, int px0)
{
    #pragma unroll
    for (int pr = 0; pr < 2; pr++) {
        const ull* A = pr ? a1 : a0;
        const int ocl = oc0 + pr * 2;
        #pragma unroll
        for (int i = 0; i < 2; i++) {
            #pragma unroll
            for (int j = 0; j < 2; j++) {
                float l0, h0, l1, h1, l2, h2, l3, h3;
                unpack2(A[(2 * i) * 4 + 2 * j],         l0, h0);
                unpack2(A[(2 * i) * 4 + 2 * j + 1],     l1, h1);
                unpack2(A[(2 * i + 1) * 4 + 2 * j],     l2, h2);
                unpack2(A[(2 * i + 1) * 4 + 2 * j + 1], l3, h3);
                const float mlo = fmaxf(fmaxf(l0, l1), fmaxf(l2, l3));
                const float mhi = fmaxf(fmaxf(h0, h1), fmaxf(h2, h3));
                dst[(ocl)     * (P * P) + (py0 + i) * P + (px0 + j)] = fmaxf(mlo, 0.0f);
                dst[(ocl + 1) * (P * P) + (py0 + i) * P + (px0 + j)] = fmaxf(mhi, 0.0f);
            }
        }
    }
}

// ---------------------------------------------------------------------------
// Fused kernel: one block per image.
// ---------------------------------------------------------------------------
__global__ __launch_bounds__(NTHREADS, 1) void qp_fused_kernel(
    const float* __restrict__ x,
    const float* __restrict__ w1g, const float* __restrict__ b1g,
    const float* __restrict__ w2g, const float* __restrict__ b2g,
    const float* __restrict__ fw,  const float* __restrict__ fb,
    float* __restrict__ out)
{
    extern __shared__ float smem[];
    float* sH1  = smem;                          // 21632
    float* sW2f = smem + H1_PER;                 // 18432 floats (float2 pairs)
    float* sImg = smem + H1_PER;                 // alias (phase 1 only)
    float* sH2  = smem + H1_PER + 18432;         // 9216

    __shared__ float  sW1f[864];                 // interleaved conv1 weight pairs
    __shared__ float2 sB1[16];
    __shared__ float2 sB2[32];
    __shared__ float  sRed[9][6];

    const int tid  = threadIdx.x;
    const int bimg = blockIdx.x;
    const float* xp = x + (size_t)bimg * X_COLS;

    // ---- stage image + conv1 weights (interleaved oc-pairs) ----
    for (int i = tid; i < N_IMG; i += NTHREADS) sImg[i] = xp[i];
    for (int l = tid; l < 864; l += NTHREADS) {
        const int oc = l / 27, r = l % 27;
        sW1f[((oc >> 1) * 27 + r) * 2 + (oc & 1)] = w1g[l];
    }
    if (tid < 16) sB1[tid] = make_float2(b1g[2 * tid], b1g[2 * tid + 1]);
    if (tid < 32) sB2[tid] = make_float2(b2g[2 * tid], b2g[2 * tid + 1]);
    __syncthreads();

    // ---- phase 1: conv1 (3->32) + relu + pool ----
    // items: 8 oc-groups(4oc) x 13x13 pooled 2x2 tiles = 1352
    {
        const ull* sW1 = reinterpret_cast<const ull*>(sW1f);
        const ull* sB1u = reinterpret_cast<const ull*>(sB1);
        for (int it = tid; it < 1352; it += NTHREADS) {
            const int g = it / 169, t = it % 169;
            const int pyt = t / 13, pxt = t % 13;
            const int y0 = pyt * 4, x0 = pxt * 4;
            ull a0[16], a1[16];
            const ull bz0 = sB1u[g * 2], bz1 = sB1u[g * 2 + 1];
            #pragma unroll
            for (int k = 0; k < 16; k++) { a0[k] = bz0; a1[k] = bz1; }
            #pragma unroll
            for (int ic = 0; ic < 3; ic++) {
                tile_ic(sImg + ic * (IMG_HW * IMG_HW) + y0 * IMG_HW + x0, IMG_HW,
                        sW1 + (g * 2) * 27 + ic * 9,
                        sW1 + (g * 2 + 1) * 27 + ic * 9, a0, a1);
            }
            pool_store<P1>(sH1, a0, a1, g * 4, pyt * 2, pxt * 2);
        }
    }
    __syncthreads();

    // ---- stage conv2 weights interleaved (overwrites image region) ----
    for (int l4 = tid * 4; l4 < 18432; l4 += NTHREADS * 4) {
        const float4 v = *reinterpret_cast<const float4*>(w2g + l4);
        const float e[4] = {v.x, v.y, v.z, v.w};
        #pragma unroll
        for (int k = 0; k < 4; k++) {
            const int l = l4 + k;
            const int oc = l / 288, r = l % 288;
            sW2f[((oc >> 1) * 288 + r) * 2 + (oc & 1)] = e[k];
        }
    }
    __syncthreads();

    // ---- phase 2: conv2 (32->64) + relu + pool ----
    // items: 16 oc-groups x 6x6 pooled 2x2 tiles = 576 (exactly 2 per thread)
    {
        const ull* sW2 = reinterpret_cast<const ull*>(sW2f);
        const ull* sB2u = reinterpret_cast<const ull*>(sB2);
        for (int it = tid; it < 576; it += NTHREADS) {
            const int g = it / 36, t = it % 36;
            const int pyt = t / 6, pxt = t % 6;
            const int y0 = pyt * 4, x0 = pxt * 4;
            ull a0[16], a1[16];
            const ull bz0 = sB2u[g * 2], bz1 = sB2u[g * 2 + 1];
            #pragma unroll
            for (int k = 0; k < 16; k++) { a0[k] = bz0; a1[k] = bz1; }
            #pragma unroll 1
            for (int ic = 0; ic < 32; ic++) {
                tile_ic(sH1 + ic * (P1 * P1) + y0 * P1 + x0, P1,
                        sW2 + (g * 2) * 288 + ic * 9,
                        sW2 + (g * 2 + 1) * 288 + ic * 9, a0, a1);
            }
            pool_store<P2>(sH2, a0, a1, g * 4, pyt * 2, pxt * 2);
        }
    }
    __syncthreads();

    // ---- phase 3: fcn (6 x 9219) + relu + 2x2 SVD clip + KKT solve ----
    {
        float acc[6] = {0.f, 0.f, 0.f, 0.f, 0.f, 0.f};
        for (int j = tid; j < H2_PER; j += NTHREADS) {
            const float hv = sH2[j];
            #pragma unroll
            for (int o = 0; o < 6; o++)
                acc[o] = fmaf(hv, fw[o * FCN_IN + j], acc[o]);
        }
        #pragma unroll
        for (int off = 16; off > 0; off >>= 1) {
            #pragma unroll
            for (int o = 0; o < 6; o++)
                acc[o] += __shfl_xor_sync(0xFFFFFFFFu, acc[o], off);
        }
        const int warp = tid >> 5, lane = tid & 31;
        if (lane == 0) {
            #pragma unroll
            for (int o = 0; o < 6; o++) sRed[warp][o] = acc[o];
        }
    }
    __syncthreads();

    if (tid == 0) {
        float yv[6];
        #pragma unroll
        for (int o = 0; o < 6; o++) {
            float s = 0.f;
            #pragma unroll
            for (int w = 0; w < 9; w++) s += sRed[w][o];
            // appended scalars: speed, dest_distance, car_distance
            #pragma unroll
            for (int k = 0; k < 3; k++)
                s = fmaf(xp[N_IMG + k], fw[o * FCN_IN + H2_PER + k], s);
            yv[o] = fmaxf(s + fb[o], 0.f);
        }

        // ---- double-precision 2x2 SVD clip + KKT (Schur) solve ----
        double A00 = yv[0], A01 = yv[1], A10 = yv[2], A11 = yv[3];
        const double b0 = yv[4], b1v = yv[5];

        const double E = 0.5 * (A00 + A11), F = 0.5 * (A00 - A11);
        const double G = 0.5 * (A10 + A01), H = 0.5 * (A10 - A01);
        const double Qh = sqrt(E * E + H * H);
        const double Rh = sqrt(F * F + G * G);
        const double s1 = Qh + Rh;
        const double s2 = fabs(Qh - Rh);

        if (s1 < 1e-300) {
            A00 = 0.01; A01 = 0.0; A10 = 0.0; A11 = 0.01;
        } else {
            const double s2c = fmax(s2, 0.1 * s1);
            if (s2c > s2) {
                // rank-1 correction: A_p = A + (s2c - s2) * u2 v2^T
                const double p = A00 * A00 + A10 * A10;
                const double r = A01 * A01 + A11 * A11;
                const double q = A00 * A01 + A10 * A11;
                const double f = 0.5 * (p - r);
                const double disc = sqrt(f * f + q * q);
                double v1x, v1y;
                if (f >= 0.0) { v1x = disc + f; v1y = q; }
                else          { v1x = q;        v1y = disc - f; }
                double inv = 1.0 / sqrt(fmax(v1x * v1x + v1y * v1y, 1e-300));
                v1x *= inv; v1y *= inv;
                double v2x = -v1y, v2y = v1x;

                const double pB = A00 * A00 + A01 * A01;
                const double rB = A10 * A10 + A11 * A11;
                const double qB = A00 * A10 + A01 * A11;
                const double fB = 0.5 * (pB - rB);
                const double discB = sqrt(fB * fB + qB * qB);
                double u1x, u1y;
                if (fB >= 0.0) { u1x = discB + fB; u1y = qB; }
                else           { u1x = qB;         u1y = discB - fB; }
                inv = 1.0 / sqrt(fmax(u1x * u1x + u1y * u1y, 1e-300));
                u1x *= inv; u1y *= inv;
                double u2x = -u1y, u2y = u1x;

                const double tsgn = u2x * (A00 * v2x + A01 * v2y)
                                  + u2y * (A10 * v2x + A11 * v2y);
                if (tsgn < 0.0) { v2x = -v2x; v2y = -v2y; }

                const double d = s2c - s2;
                A00 += d * u2x * v2x; A01 += d * u2x * v2y;
                A10 += d * u2y * v2x; A11 += d * u2y * v2y;
            }
        }

        // Q = diag(1, 0.5), p = (0, -1000) -> z0 = (0, 2000)
        const double qi0 = 1.0, qi1 = 2.0;
        const double S00 = A00 * A00 * qi0 + A01 * A01 * qi1;
        const double S01 = A00 * A10 * qi0 + A01 * A11 * qi1;
        const double S11 = A10 * A10 * qi0 + A11 * A11 * qi1;
        const double r0 = A01 * 2000.0 - b0;
        const double r1 = A11 * 2000.0 - b1v;
        const double idet = 1.0 / (S00 * S11 - S01 * S01);
        const double l0 = (S11 * r0 - S01 * r1) * idet;
        const double l1 = (S00 * r1 - S01 * r0) * idet;
        out[bimg * 2 + 0] = (float)(-qi0 * (A00 * l0 + A10 * l1));
        out[bimg * 2 + 1] = (float)(2000.0 - qi1 * (A01 * l0 + A11 * l1));
    }
}

// ---------------------------------------------------------------------------
// Launcher (graph-capturable)
// ---------------------------------------------------------------------------
extern "C" void kernel_launch(void* const* d_in, const int* in_sizes, int n_in,
                              void* d_out, int out_size)
{
    const float* x  = (const float*)d_in[0];
    const float* w1 = (const float*)d_in[1];
    const float* b1 = (const float*)d_in[2];
    const float* w2 = (const float*)d_in[3];
    const float* b2 = (const float*)d_in[4];
    const float* fw = (const float*)d_in[5];
    const float* fb = (const float*)d_in[6];
    float* out = (float*)d_out;

    cudaFuncSetAttribute(qp_fused_kernel,
                         cudaFuncAttributeMaxDynamicSharedMemorySize, SMEM_BYTES);
    qp_fused_kernel<<<BATCH, NTHREADS, SMEM_BYTES>>>(x, w1, b1, w2, b2, fw, fb, out);
}